// round 1
// baseline (speedup 1.0000x reference)
#include <cuda_runtime.h>

#define NFEAT 262144
#define NTGT  8192
#define NLAT  32
#define NB    64
#define NTH   512
#define FB4   (NFEAT/NB/4)   /* 1024 float4 per block */
#define F4T   (FB4/NTH)      /* 2 float4 per thread   */
#define TB4   (NTGT/NB/4)    /* 32 float4 per block   */
#define EPSV  1e-7f

/* output offsets (floats) */
#define OFF_MUY  (NFEAT)
#define OFF_U    (NFEAT + NTGT)
#define OFF_WZ   (OFF_U + NLAT)
#define OFF_CZ   (OFF_WZ + NLAT*NFEAT)
#define OFF_TSS  (OFF_CZ + NLAT*NTGT)
#define OFF_BZ   (OFF_TSS + NLAT)
#define OFF_P    (OFF_BZ + NLAT)

/* per-phase global accumulators: [comp][phase 0..3][2 sums] */
__device__ float    g_partial[NLAT*4*2];
__device__ unsigned g_arrive;   /* returns to 0 after every barrier  */
__device__ unsigned g_flag;     /* monotone release counter          */

__device__ __forceinline__ float volr(const float* p){
  return *((volatile const float*)p);
}

/* self-resetting grid barrier: safe across graph replays */
__device__ __forceinline__ void gridbar(){
  __syncthreads();
  if (threadIdx.x == 0){
    __threadfence();
    volatile unsigned* vf = (volatile unsigned*)&g_flag;
    unsigned old = *vf;
    if (atomicAdd(&g_arrive, 1u) == (unsigned)(NB-1)){
      atomicExch(&g_arrive, 0u);
      __threadfence();
      atomicAdd(&g_flag, 1u);
    } else {
      while (*vf == old) { }
    }
    __threadfence();
  }
  __syncthreads();
}

__device__ __forceinline__ float d4(float4 a, float4 b){
  return fmaf(a.x,b.x, fmaf(a.y,b.y, fmaf(a.z,b.z, a.w*b.w)));
}
__device__ __forceinline__ float4 f4fma(float4 a, float s, float4 b){
  float4 r; r.x=fmaf(a.x,s,b.x); r.y=fmaf(a.y,s,b.y);
  r.z=fmaf(a.z,s,b.z); r.w=fmaf(a.w,s,b.w); return r;
}

/* block-reduce two floats, thread 0 atomically accumulates into slot */
__device__ __forceinline__ void red_acc(float a, float b, int slot, float* s_red){
  #pragma unroll
  for (int o=16;o>0;o>>=1){
    a += __shfl_xor_sync(0xffffffffu, a, o);
    b += __shfl_xor_sync(0xffffffffu, b, o);
  }
  int w = threadIdx.x >> 5;
  if ((threadIdx.x & 31) == 0){ s_red[w] = a; s_red[16+w] = b; }
  __syncthreads();
  if (threadIdx.x < 32){
    float aa = (threadIdx.x < (NTH/32)) ? s_red[threadIdx.x]      : 0.f;
    float bb = (threadIdx.x < (NTH/32)) ? s_red[16+threadIdx.x]   : 0.f;
    #pragma unroll
    for (int o=8;o>0;o>>=1){
      aa += __shfl_xor_sync(0xffffffffu, aa, o);
      bb += __shfl_xor_sync(0xffffffffu, bb, o);
    }
    if (threadIdx.x == 0){
      atomicAdd(&g_partial[2*slot],   aa);
      atomicAdd(&g_partial[2*slot+1], bb);
    }
  }
}

__global__ void __launch_bounds__(NTH, 1)
ipls_kernel(const float* __restrict__ x,      const float* __restrict__ y,
            const float* __restrict__ mux,    const float* __restrict__ muy,
            const float* __restrict__ u_in,   const float* __restrict__ Wz_in,
            const float* __restrict__ Cz_in,  const float* __restrict__ tss_in,
            const float* __restrict__ bz_in,  const float* __restrict__ P_in,
            const int* __restrict__ n_in,     float* __restrict__ out)
{
  __shared__ float4 s_xr[FB4];   /* block-owned xr slice (16 KB)      */
  __shared__ float4 s_wz[FB4];   /* raw Wz row slice cache (16 KB)    */
  __shared__ float4 s_yr[TB4];   /* block-owned yr slice              */
  __shared__ float4 s_cz[TB4];   /* raw Cz row slice cache            */
  __shared__ float  s_red[32];

  const int tid = threadIdx.x, bid = blockIdx.x;
  const int n   = n_in[0];
  const float fn1  = (float)(n + 1);
  const float fden = (float)(n + 2);

  /* ---- init: mu updates + centered residuals into SMEM ---- */
  {
    const float4* X4 = (const float4*)x;
    const float4* M4 = (const float4*)mux;
    float4* Omux = (float4*)out;
    #pragma unroll
    for (int j=0;j<F4T;j++){
      int li = j*NTH + tid;
      int gi = bid*FB4 + li;
      float4 xv = X4[gi], mv = M4[gi];
      float4 mu;
      mu.x = (mv.x*fn1 + xv.x)/fden; mu.y = (mv.y*fn1 + xv.y)/fden;
      mu.z = (mv.z*fn1 + xv.z)/fden; mu.w = (mv.w*fn1 + xv.w)/fden;
      Omux[gi] = mu;
      float4 xr; xr.x=xv.x-mu.x; xr.y=xv.y-mu.y; xr.z=xv.z-mu.z; xr.w=xv.w-mu.w;
      s_xr[li] = xr;
    }
    if (tid < TB4){
      int gi = bid*TB4 + tid;
      float4 yv = ((const float4*)y)[gi];
      float4 mv = ((const float4*)muy)[gi];
      float4 mu;
      mu.x = (mv.x*fn1 + yv.x)/fden; mu.y = (mv.y*fn1 + yv.y)/fden;
      mu.z = (mv.z*fn1 + yv.z)/fden; mu.w = (mv.w*fn1 + yv.w)/fden;
      ((float4*)(out + OFF_MUY))[gi] = mu;
      float4 yr; yr.x=yv.x-mu.x; yr.y=yv.y-mu.y; yr.z=yv.z-mu.z; yr.w=yv.w-mu.w;
      s_yr[tid] = yr;
    }
    /* zero this launch's accumulator slots (NB*4 == 256 == total slots) */
    if (tid < 4) *((volatile float*)&g_partial[bid*4 + tid]) = 0.f;
  }
  gridbar();

  /* ---- burn-in path (n_new <= 3): only Wz and t_sq_sum change ---- */
  if (n + 1 <= 3){
    for (int c=0;c<NLAT;c++){
      float u_c = u_in[c];
      const float4* Wr = (const float4*)(Wz_in + (size_t)c*NFEAT) + (size_t)bid*FB4;
      float4* Wo = (float4*)(out + OFF_WZ) + (size_t)c*(NFEAT/4) + (size_t)bid*FB4;
      float s1=0.f, s2=0.f;
      #pragma unroll
      for (int j=0;j<F4T;j++){
        int li = j*NTH + tid;
        float4 w  = Wr[li];
        float4 xr = s_xr[li];
        float4 wz = f4fma(xr, u_c, w);
        Wo[li] = wz;
        s1 += d4(xr, wz); s2 += d4(wz, wz);
      }
      red_acc(s1, s2, c*4, s_red);
      __syncthreads();
    }
    gridbar();
    if (bid==0 && tid<NLAT){
      int c = tid;
      float S1 = volr(&g_partial[2*(c*4)]);
      float S2 = volr(&g_partial[2*(c*4)+1]);
      float tz = S1 / (sqrtf(S2) + EPSV);
      out[OFF_TSS + c] = tss_in[c] + tz*tz;
      out[OFF_U   + c] = u_in[c];
      out[OFF_BZ  + c] = bz_in[c];
    }
    int g = bid*NTH + tid;
    {
      const float4* Ci = (const float4*)Cz_in;
      float4* Co = (float4*)(out + OFF_CZ);
      #pragma unroll
      for (int k=0;k<(NLAT*NTGT/4)/(NB*NTH);k++)
        Co[k*NB*NTH + g] = Ci[k*NB*NTH + g];
      const float4* Pi = (const float4*)P_in;
      float4* Po = (float4*)(out + OFF_P);
      for (int k=0;k<(NLAT*NFEAT/4)/(NB*NTH);k++)
        Po[k*NB*NTH + g] = Pi[k*NB*NTH + g];
    }
    return;
  }

  /* ---- main scan over 32 components ---- */
  for (int c=0;c<NLAT;c++){
    float u_i        = u_in[c];
    const float tss0 = tss_in[c];

    /* phase 0: inner iter 1, feature pass (stream Wz, cache raw in smem) */
    float s1=0.f, s2=0.f;
    {
      const float4* Wr = (const float4*)(Wz_in + (size_t)c*NFEAT) + (size_t)bid*FB4;
      #pragma unroll
      for (int j=0;j<F4T;j++){
        int li = j*NTH + tid;
        float4 w  = Wr[li];
        s_wz[li]  = w;
        float4 xr = s_xr[li];
        float4 wz = f4fma(xr, u_i, w);
        s1 += d4(xr, wz); s2 += d4(wz, wz);
      }
    }
    red_acc(s1, s2, c*4+0, s_red);
    gridbar();
    float S1 = volr(&g_partial[2*(c*4+0)]);
    float S2 = volr(&g_partial[2*(c*4+0)+1]);
    float tz   = S1 / (sqrtf(S2) + EPSV);
    float tss_ = tss0 + tz*tz;
    float t    = tz / sqrtf(tss_);

    /* phase 1: inner iter 1, target pass (cache raw Cz in smem) */
    float c2=0.f, cy=0.f;
    if (tid < TB4){
      float4 c0 = ((const float4*)(Cz_in + (size_t)c*NTGT))[bid*TB4 + tid];
      s_cz[tid] = c0;
      float4 yr = s_yr[tid];
      float4 cz = f4fma(yr, t, c0);
      c2 += d4(cz, cz); cy += d4(yr, cz);
    }
    red_acc(c2, cy, c*4+1, s_red);
    gridbar();
    {
      float C2 = volr(&g_partial[2*(c*4+1)]);
      float CY = volr(&g_partial[2*(c*4+1)+1]);
      u_i = CY / sqrtf(C2);
    }

    /* phase 2: inner iter 2, feature pass (Wz from smem cache), write Wz out */
    s1 = 0.f; s2 = 0.f;
    {
      float4* Wo = (float4*)(out + OFF_WZ) + (size_t)c*(NFEAT/4) + (size_t)bid*FB4;
      #pragma unroll
      for (int j=0;j<F4T;j++){
        int li = j*NTH + tid;
        float4 w  = s_wz[li];
        float4 xr = s_xr[li];
        float4 wz = f4fma(xr, u_i, w);
        Wo[li] = wz;
        s1 += d4(xr, wz); s2 += d4(wz, wz);
      }
    }
    red_acc(s1, s2, c*4+2, s_red);
    gridbar();
    S1 = volr(&g_partial[2*(c*4+2)]);
    S2 = volr(&g_partial[2*(c*4+2)+1]);
    tz   = S1 / (sqrtf(S2) + EPSV);
    tss_ = tss0 + tz*tz;
    t    = tz / sqrtf(tss_);

    /* phase 3: iter-2 target pass (write Cz out) + P update + xr deflate */
    c2 = 0.f; cy = 0.f;
    if (tid < TB4){
      float4 c0 = s_cz[tid];
      float4 yr = s_yr[tid];
      float4 cz = f4fma(yr, t, c0);
      ((float4*)(out + OFF_CZ) + (size_t)c*(NTGT/4))[bid*TB4 + tid] = cz;
      c2 += d4(cz, cz); cy += d4(yr, cz);
    }
    {
      const float4* Pr = (const float4*)(P_in + (size_t)c*NFEAT) + (size_t)bid*FB4;
      float4* Po = (float4*)(out + OFF_P) + (size_t)c*(NFEAT/4) + (size_t)bid*FB4;
      #pragma unroll
      for (int j=0;j<F4T;j++){
        int li = j*NTH + tid;
        float4 p  = Pr[li];
        float4 xr = s_xr[li];
        float4 pn = f4fma(xr, t, p);
        Po[li] = pn;
        xr = f4fma(pn, -t, xr);        /* xr -= t * P_new */
        s_xr[li] = xr;
      }
    }
    red_acc(c2, cy, c*4+3, s_red);
    gridbar();
    {
      float C2 = volr(&g_partial[2*(c*4+3)]);
      float CY = volr(&g_partial[2*(c*4+3)+1]);
      u_i = CY / sqrtf(C2);
      float bz_new = bz_in[c] + u_i*tz;
      float b  = bz_new / sqrtf(tss_);
      float kk = b * t / sqrtf(C2);    /* b*t/||cz|| */
      if (tid < TB4){
        float4 c0 = s_cz[tid];
        float4 yr = s_yr[tid];
        float4 cz = f4fma(yr, t, c0);
        yr = f4fma(cz, -kk, yr);       /* yr -= b*t*C_i */
        s_yr[tid] = yr;
      }
      if (bid == 0 && tid == 0){
        out[OFF_U   + c] = u_i;
        out[OFF_TSS + c] = tss_;
        out[OFF_BZ  + c] = bz_new;
      }
    }
    /* block-local state (s_xr, s_yr) updated by owning threads only —
       no extra grid barrier needed before the next component */
  }
}

extern "C" void kernel_launch(void* const* d_in, const int* in_sizes, int n_in,
                              void* d_out, int out_size)
{
  (void)in_sizes; (void)n_in; (void)out_size;
  ipls_kernel<<<NB, NTH>>>(
      (const float*)d_in[0],  (const float*)d_in[1],
      (const float*)d_in[2],  (const float*)d_in[3],
      (const float*)d_in[4],  (const float*)d_in[5],
      (const float*)d_in[6],  (const float*)d_in[7],
      (const float*)d_in[8],  (const float*)d_in[9],
      (const int*)  d_in[10], (float*)d_out);
}

// round 2
// speedup vs baseline: 1.6043x; 1.6043x over previous
#include <cuda_runtime.h>

#define NFEAT 262144
#define NTGT  8192
#define NLAT  32
#define NB    128
#define NTH   512
#define FB4   (NFEAT/NB/4)   /* 512 float4 per block = 1 per thread */
#define YF4   (NTGT/4)       /* 2048 float4 = full target vector    */
#define YIT   (YF4/NTH)      /* 4 float4 per thread                 */
#define YSL   (YF4/NB)       /* 16 float4 block slice of muy        */
#define EPSV  1e-7f

/* output offsets (floats) */
#define OFF_MUY  (NFEAT)
#define OFF_U    (NFEAT + NTGT)
#define OFF_WZ   (OFF_U + NLAT)
#define OFF_CZ   (OFF_WZ + NLAT*NFEAT)
#define OFF_TSS  (OFF_CZ + NLAT*NTGT)
#define OFF_BZ   (OFF_TSS + NLAT)
#define OFF_P    (OFF_BZ + NLAT)

/* 64 float-pair slots: [comp][phase A/B][2 sums] = 128 floats */
__device__ float    g_partial[NLAT*2*2];
__device__ unsigned g_arrive;
__device__ unsigned g_flag;

static __device__ __forceinline__ float volr(const float* p){
  return *((volatile const float*)p);
}

/* self-resetting grid barrier: safe across graph replays */
static __device__ __forceinline__ void gridbar(){
  __syncthreads();
  if (threadIdx.x == 0){
    __threadfence();
    volatile unsigned* vf = (volatile unsigned*)&g_flag;
    unsigned old = *vf;
    if (atomicAdd(&g_arrive, 1u) == (unsigned)(NB-1)){
      atomicExch(&g_arrive, 0u);
      __threadfence();
      atomicAdd(&g_flag, 1u);
    } else {
      while (*vf == old) { }
    }
    __threadfence();
  }
  __syncthreads();
}

static __device__ __forceinline__ float d4(float4 a, float4 b){
  return fmaf(a.x,b.x, fmaf(a.y,b.y, fmaf(a.z,b.z, a.w*b.w)));
}
static __device__ __forceinline__ float4 f4fma(float4 a, float s, float4 b){
  float4 r; r.x=fmaf(a.x,s,b.x); r.y=fmaf(a.y,s,b.y);
  r.z=fmaf(a.z,s,b.z); r.w=fmaf(a.w,s,b.w); return r;
}

/* block-reduce two floats, thread 0 atomically accumulates into global slot */
static __device__ __forceinline__ void red_acc(float a, float b, int slot, float* s_red){
  __syncthreads();
  #pragma unroll
  for (int o=16;o>0;o>>=1){
    a += __shfl_xor_sync(0xffffffffu, a, o);
    b += __shfl_xor_sync(0xffffffffu, b, o);
  }
  int w = threadIdx.x >> 5;
  if ((threadIdx.x & 31) == 0){ s_red[w] = a; s_red[16+w] = b; }
  __syncthreads();
  if (threadIdx.x < 32){
    float aa = (threadIdx.x < 16) ? s_red[threadIdx.x]    : 0.f;
    float bb = (threadIdx.x < 16) ? s_red[16+threadIdx.x] : 0.f;
    #pragma unroll
    for (int o=8;o>0;o>>=1){
      aa += __shfl_xor_sync(0xffffffffu, aa, o);
      bb += __shfl_xor_sync(0xffffffffu, bb, o);
    }
    if (threadIdx.x == 0){
      atomicAdd(&g_partial[2*slot],   aa);
      atomicAdd(&g_partial[2*slot+1], bb);
    }
  }
}

/* block-local reduce two floats, result broadcast to ALL threads
   (identical inputs/order in every block -> bit-identical results) */
static __device__ __forceinline__ void bred2(float& a, float& b, float* s_red){
  __syncthreads();
  #pragma unroll
  for (int o=16;o>0;o>>=1){
    a += __shfl_xor_sync(0xffffffffu, a, o);
    b += __shfl_xor_sync(0xffffffffu, b, o);
  }
  int w = threadIdx.x >> 5;
  if ((threadIdx.x & 31) == 0){ s_red[w] = a; s_red[16+w] = b; }
  __syncthreads();
  if (threadIdx.x < 32){
    float aa = (threadIdx.x < 16) ? s_red[threadIdx.x]    : 0.f;
    float bb = (threadIdx.x < 16) ? s_red[16+threadIdx.x] : 0.f;
    #pragma unroll
    for (int o=8;o>0;o>>=1){
      aa += __shfl_xor_sync(0xffffffffu, aa, o);
      bb += __shfl_xor_sync(0xffffffffu, bb, o);
    }
    if (threadIdx.x == 0){ s_red[0] = aa; s_red[16] = bb; }
  }
  __syncthreads();
  a = s_red[0]; b = s_red[16];
}

__global__ void __launch_bounds__(NTH, 1)
ipls_kernel(const float* __restrict__ x,      const float* __restrict__ y,
            const float* __restrict__ mux,    const float* __restrict__ muy,
            const float* __restrict__ u_in,   const float* __restrict__ Wz_in,
            const float* __restrict__ Cz_in,  const float* __restrict__ tss_in,
            const float* __restrict__ bz_in,  const float* __restrict__ P_in,
            const int* __restrict__ n_in,     float* __restrict__ out)
{
  __shared__ float s_red[32];

  const int tid = threadIdx.x, bid = blockIdx.x;
  const int n   = n_in[0];
  const float fn1  = (float)(n + 1);
  const float fden = (float)(n + 2);

  /* zero my accumulator float (128 floats == NB blocks) */
  if (tid == 0) *((volatile float*)&g_partial[bid]) = 0.f;

  /* ---- init: feature slice (1 float4/thread, lives in a register) ---- */
  float4 xr;
  {
    int gi = bid*FB4 + tid;
    float4 xv = ((const float4*)x)[gi];
    float4 mv = ((const float4*)mux)[gi];
    float4 mu;
    mu.x = (mv.x*fn1 + xv.x)/fden; mu.y = (mv.y*fn1 + xv.y)/fden;
    mu.z = (mv.z*fn1 + xv.z)/fden; mu.w = (mv.w*fn1 + xv.w)/fden;
    ((float4*)out)[gi] = mu;
    xr.x = xv.x-mu.x; xr.y = xv.y-mu.y; xr.z = xv.z-mu.z; xr.w = xv.w-mu.w;
  }

  /* ---- init: FULL yr in registers (redundant in every block) ---- */
  float4 yr[YIT];
  #pragma unroll
  for (int k=0;k<YIT;k++){
    int gi = k*NTH + tid;
    float4 yv = ((const float4*)y)[gi];
    float4 mv = ((const float4*)muy)[gi];
    float4 mu;
    mu.x = (mv.x*fn1 + yv.x)/fden; mu.y = (mv.y*fn1 + yv.y)/fden;
    mu.z = (mv.z*fn1 + yv.z)/fden; mu.w = (mv.w*fn1 + yv.w)/fden;
    yr[k].x = yv.x-mu.x; yr[k].y = yv.y-mu.y;
    yr[k].z = yv.z-mu.z; yr[k].w = yv.w-mu.w;
  }
  /* muy out: block writes its own 1/NB slice */
  if (tid < YSL){
    int gi = bid*YSL + tid;
    float4 yv = ((const float4*)y)[gi];
    float4 mv = ((const float4*)muy)[gi];
    float4 mu;
    mu.x = (mv.x*fn1 + yv.x)/fden; mu.y = (mv.y*fn1 + yv.y)/fden;
    mu.z = (mv.z*fn1 + yv.z)/fden; mu.w = (mv.w*fn1 + yv.w)/fden;
    ((float4*)(out + OFF_MUY))[gi] = mu;
  }

  /* prefetch Wz row 0 slice */
  float4 wnext = ((const float4*)Wz_in)[bid*FB4 + tid];

  gridbar();   /* accumulators zeroed + (burn-in) ordering */

  /* ---- burn-in path (n_new <= 3): only Wz and t_sq_sum change ---- */
  if (n + 1 <= 3){
    for (int c=0;c<NLAT;c++){
      float u_c = u_in[c];
      float4 w = (c==0) ? wnext
               : ((const float4*)Wz_in)[(size_t)c*(NFEAT/4) + bid*FB4 + tid];
      float4 wz = f4fma(xr, u_c, w);
      ((float4*)(out + OFF_WZ))[(size_t)c*(NFEAT/4) + bid*FB4 + tid] = wz;
      red_acc(d4(xr,wz), d4(wz,wz), 2*c, s_red);
    }
    gridbar();
    if (bid==0 && tid<NLAT){
      int c = tid;
      float S1 = volr(&g_partial[4*c]);
      float S2 = volr(&g_partial[4*c+1]);
      float tz = S1 / (sqrtf(S2) + EPSV);
      out[OFF_TSS + c] = tss_in[c] + tz*tz;
      out[OFF_U   + c] = u_in[c];
      out[OFF_BZ  + c] = bz_in[c];
    }
    int g = bid*NTH + tid;
    ((float4*)(out + OFF_CZ))[g] = ((const float4*)Cz_in)[g];
    const float4* Pi = (const float4*)P_in;
    float4* Po = (float4*)(out + OFF_P);
    #pragma unroll 4
    for (int k=0;k<(NLAT*NFEAT/4)/(NB*NTH);k++)
      Po[k*NB*NTH + g] = Pi[k*NB*NTH + g];
    return;
  }

  /* ---- main scan over 32 components: 2 grid barriers each ---- */
  for (int c=0;c<NLAT;c++){
    float u_i        = u_in[c];
    const float tss0 = tss_in[c];
    const size_t frow = (size_t)c*(NFEAT/4) + bid*FB4 + tid;

    /* phase A: feature pass 1 + prefetch P slice and Cz row */
    float4 w  = wnext;
    float4 wz = f4fma(xr, u_i, w);
    float s1 = d4(xr,wz), s2 = d4(wz,wz);
    float4 pcur = ((const float4*)P_in)[frow];       /* used after barrier 2 */
    float4 c0[YIT];
    #pragma unroll
    for (int k=0;k<YIT;k++)                          /* used after barrier 1 */
      c0[k] = ((const float4*)Cz_in)[(size_t)c*YF4 + k*NTH + tid];
    red_acc(s1, s2, 2*c, s_red);
    gridbar();
    float S1 = volr(&g_partial[4*c]);
    float S2 = volr(&g_partial[4*c+1]);
    float tz   = S1 / (sqrtf(S2) + EPSV);
    float tss_ = tss0 + tz*tz;
    float t    = tz / sqrtf(tss_);

    /* local target pass 1 (block-redundant, no global sync) */
    float c2=0.f, cy=0.f;
    #pragma unroll
    for (int k=0;k<YIT;k++){
      float4 cz = f4fma(yr[k], t, c0[k]);
      c2 += d4(cz,cz); cy += d4(yr[k],cz);
    }
    bred2(c2, cy, s_red);
    u_i = cy / sqrtf(c2);

    /* phase B: feature pass 2, write Wz, prefetch next Wz */
    wz = f4fma(xr, u_i, w);
    ((float4*)(out + OFF_WZ))[frow] = wz;
    s1 = d4(xr,wz); s2 = d4(wz,wz);
    if (c+1 < NLAT)
      wnext = ((const float4*)Wz_in)[(size_t)(c+1)*(NFEAT/4) + bid*FB4 + tid];
    red_acc(s1, s2, 2*c+1, s_red);
    gridbar();
    S1 = volr(&g_partial[4*c+2]);
    S2 = volr(&g_partial[4*c+3]);
    tz   = S1 / (sqrtf(S2) + EPSV);
    tss_ = tss0 + tz*tz;
    t    = tz / sqrtf(tss_);

    /* local tail: target pass 2, scalars, deflations, P update */
    float4 czk[YIT];
    c2 = 0.f; cy = 0.f;
    #pragma unroll
    for (int k=0;k<YIT;k++){
      czk[k] = f4fma(yr[k], t, c0[k]);
      c2 += d4(czk[k],czk[k]); cy += d4(yr[k],czk[k]);
    }
    bred2(c2, cy, s_red);
    float u_f    = cy / sqrtf(c2);
    float bz_new = bz_in[c] + u_f*tz;
    float b      = bz_new / sqrtf(tss_);
    float kk     = b * t / sqrtf(c2);     /* b*t/||cz|| */

    if (bid == c){                         /* one writer block per component */
      #pragma unroll
      for (int k=0;k<YIT;k++)
        ((float4*)(out + OFF_CZ))[(size_t)c*YF4 + k*NTH + tid] = czk[k];
      if (tid == 0){
        out[OFF_U   + c] = u_f;
        out[OFF_TSS + c] = tss_;
        out[OFF_BZ  + c] = bz_new;
      }
    }
    #pragma unroll
    for (int k=0;k<YIT;k++)
      yr[k] = f4fma(czk[k], -kk, yr[k]);   /* yr -= b*t*C_i */

    float4 pn = f4fma(xr, t, pcur);        /* P_new = P + xr*t */
    ((float4*)(out + OFF_P))[frow] = pn;
    xr = f4fma(pn, -t, xr);                /* xr -= t*P_new */
  }
}

extern "C" void kernel_launch(void* const* d_in, const int* in_sizes, int n_in,
                              void* d_out, int out_size)
{
  (void)in_sizes; (void)n_in; (void)out_size;
  ipls_kernel<<<NB, NTH>>>(
      (const float*)d_in[0],  (const float*)d_in[1],
      (const float*)d_in[2],  (const float*)d_in[3],
      (const float*)d_in[4],  (const float*)d_in[5],
      (const float*)d_in[6],  (const float*)d_in[7],
      (const float*)d_in[8],  (const float*)d_in[9],
      (const int*)  d_in[10], (float*)d_out);
}

// round 3
// speedup vs baseline: 2.2454x; 1.3996x over previous
#include <cuda_runtime.h>

#define NFEAT 262144
#define NTGT  8192
#define NLAT  32
#define NB    128
#define NTH   512
#define FB4   (NFEAT/NB/4)   /* 512 float4 per block = 1 per thread */
#define YF4   (NTGT/4)       /* 2048 float4 = full target vector    */
#define YIT   (YF4/NTH)      /* 4 float4 per thread                 */
#define YSL   (YF4/NB)       /* 16 float4 block slice of muy        */
#define EPSV  1e-7f

/* output offsets (floats) */
#define OFF_MUY  (NFEAT)
#define OFF_U    (NFEAT + NTGT)
#define OFF_WZ   (OFF_U + NLAT)
#define OFF_CZ   (OFF_WZ + NLAT*NFEAT)
#define OFF_TSS  (OFF_CZ + NLAT*NTGT)
#define OFF_BZ   (OFF_TSS + NLAT)
#define OFF_P    (OFF_BZ + NLAT)

/* per-(component, block) mailbox: (A, B, Q, pad) — written once per launch */
__device__ float4   g_part[NLAT*NB];
/* per-block monotone signal word (epoch base + phase); never reset */
__device__ unsigned g_sig[NB];

static __device__ __forceinline__ void stv4(float4* p, float4 v){
  asm volatile("st.volatile.global.v4.f32 [%0], {%1,%2,%3,%4};"
               :: "l"(p), "f"(v.x), "f"(v.y), "f"(v.z), "f"(v.w) : "memory");
}
static __device__ __forceinline__ float4 ldv4(const float4* p){
  float4 v;
  asm volatile("ld.volatile.global.v4.f32 {%0,%1,%2,%3}, [%4];"
               : "=f"(v.x), "=f"(v.y), "=f"(v.z), "=f"(v.w) : "l"(p) : "memory");
  return v;
}
static __device__ __forceinline__ unsigned ldvu(const unsigned* p){
  unsigned v;
  asm volatile("ld.volatile.global.u32 %0, [%1];" : "=r"(v) : "l"(p) : "memory");
  return v;
}
static __device__ __forceinline__ void stvu(unsigned* p, unsigned v){
  asm volatile("st.volatile.global.u32 [%0], %1;" :: "l"(p), "r"(v) : "memory");
}

static __device__ __forceinline__ float d4(float4 a, float4 b){
  return fmaf(a.x,b.x, fmaf(a.y,b.y, fmaf(a.z,b.z, a.w*b.w)));
}
static __device__ __forceinline__ float4 f4fma(float4 a, float s, float4 b){
  float4 r; r.x=fmaf(a.x,s,b.x); r.y=fmaf(a.y,s,b.y);
  r.z=fmaf(a.z,s,b.z); r.w=fmaf(a.w,s,b.w); return r;
}

/* block-wide reduce of 3 floats; result broadcast to ALL 512 threads.
   identical order in every block -> bit-identical results */
static __device__ __forceinline__ float4 bred_all(float a, float b, float c, float4* s_w){
  #pragma unroll
  for (int o=16;o>0;o>>=1){
    a += __shfl_xor_sync(0xffffffffu, a, o);
    b += __shfl_xor_sync(0xffffffffu, b, o);
    c += __shfl_xor_sync(0xffffffffu, c, o);
  }
  if ((threadIdx.x & 31) == 0) s_w[threadIdx.x >> 5] = make_float4(a,b,c,0.f);
  __syncthreads();
  float4 r = s_w[0];
  #pragma unroll
  for (int w=1;w<16;w++){ float4 t = s_w[w]; r.x+=t.x; r.y+=t.y; r.z+=t.z; }
  __syncthreads();
  return r;
}

/* wait for all NB blocks to post phase `sigval` for component c,
   then sum their (A,B,Q) partials; result broadcast to all threads */
static __device__ __forceinline__ float4 grid_gather(int c, unsigned sigval, float4* s_w){
  float a=0.f, b=0.f, q=0.f;
  if (threadIdx.x < NB){
    const unsigned* sp = &g_sig[threadIdx.x];
    while (ldvu(sp) < sigval) { }
    float4 p = ldv4(&g_part[c*NB + threadIdx.x]);
    a=p.x; b=p.y; q=p.z;
    #pragma unroll
    for (int o=16;o>0;o>>=1){
      a += __shfl_xor_sync(0xffffffffu, a, o);
      b += __shfl_xor_sync(0xffffffffu, b, o);
      q += __shfl_xor_sync(0xffffffffu, q, o);
    }
    if ((threadIdx.x & 31) == 0) s_w[threadIdx.x >> 5] = make_float4(a,b,q,0.f);
  }
  __syncthreads();
  float4 r = s_w[0];
  #pragma unroll
  for (int w=1;w<4;w++){ float4 t = s_w[w]; r.x+=t.x; r.y+=t.y; r.z+=t.z; }
  __syncthreads();
  return r;
}

__global__ void __launch_bounds__(NTH, 1)
ipls_kernel(const float* __restrict__ x,      const float* __restrict__ y,
            const float* __restrict__ mux,    const float* __restrict__ muy,
            const float* __restrict__ u_in,   const float* __restrict__ Wz_in,
            const float* __restrict__ Cz_in,  const float* __restrict__ tss_in,
            const float* __restrict__ bz_in,  const float* __restrict__ P_in,
            const int* __restrict__ n_in,     float* __restrict__ out)
{
  __shared__ float4 s_w[16];

  const int tid = threadIdx.x, bid = blockIdx.x;
  /* epoch base: all slots hold the same value at launch start (monotone) */
  const unsigned base = ldvu(&g_sig[bid]);

  const int n   = n_in[0];
  const float fn1  = (float)(n + 1);
  const float fden = (float)(n + 2);

  /* ---- init: feature slice (1 float4/thread, register-resident) ---- */
  float4 xr;
  {
    int gi = bid*FB4 + tid;
    float4 xv = ((const float4*)x)[gi];
    float4 mv = ((const float4*)mux)[gi];
    float4 mu;
    mu.x = (mv.x*fn1 + xv.x)/fden; mu.y = (mv.y*fn1 + xv.y)/fden;
    mu.z = (mv.z*fn1 + xv.z)/fden; mu.w = (mv.w*fn1 + xv.w)/fden;
    ((float4*)out)[gi] = mu;
    xr.x = xv.x-mu.x; xr.y = xv.y-mu.y; xr.z = xv.z-mu.z; xr.w = xv.w-mu.w;
  }

  /* ---- init: FULL yr in registers (block-redundant) ---- */
  float4 yr[YIT];
  #pragma unroll
  for (int k=0;k<YIT;k++){
    int gi = k*NTH + tid;
    float4 yv = ((const float4*)y)[gi];
    float4 mv = ((const float4*)muy)[gi];
    float4 mu;
    mu.x = (mv.x*fn1 + yv.x)/fden; mu.y = (mv.y*fn1 + yv.y)/fden;
    mu.z = (mv.z*fn1 + yv.z)/fden; mu.w = (mv.w*fn1 + yv.w)/fden;
    yr[k].x = yv.x-mu.x; yr[k].y = yv.y-mu.y;
    yr[k].z = yv.z-mu.z; yr[k].w = yv.w-mu.w;
  }
  /* muy out: each block writes its own 1/NB slice */
  if (tid < YSL){
    int gi = bid*YSL + tid;
    float4 yv = ((const float4*)y)[gi];
    float4 mv = ((const float4*)muy)[gi];
    float4 mu;
    mu.x = (mv.x*fn1 + yv.x)/fden; mu.y = (mv.y*fn1 + yv.y)/fden;
    mu.z = (mv.z*fn1 + yv.z)/fden; mu.w = (mv.w*fn1 + yv.w)/fden;
    ((float4*)(out + OFF_MUY))[gi] = mu;
  }

  /* prefetch Wz row 0 slice */
  float4 wnext = ((const float4*)Wz_in)[bid*FB4 + tid];

  /* ---- burn-in path (n_new <= 3): only Wz and t_sq_sum change ---- */
  if (n + 1 <= 3){
    for (int c=0;c<NLAT;c++){
      float u_c = u_in[c];
      float4 w = (c==0) ? wnext
               : ((const float4*)Wz_in)[(size_t)c*(NFEAT/4) + bid*FB4 + tid];
      float4 wz = f4fma(xr, u_c, w);
      ((float4*)(out + OFF_WZ))[(size_t)c*(NFEAT/4) + bid*FB4 + tid] = wz;
      float4 r = bred_all(d4(xr,wz), d4(wz,wz), 0.f, s_w);
      if (tid == 0) stv4(&g_part[c*NB + bid], r);
    }
    if (tid == 0){ __threadfence(); stvu(&g_sig[bid], base + NLAT); }

    if (bid == 0){
      for (int c=0;c<NLAT;c++){
        float4 r = grid_gather(c, base + NLAT, s_w);
        if (tid == 0){
          float tzb = r.x / (sqrtf(r.y) + EPSV);
          out[OFF_TSS + c] = tss_in[c] + tzb*tzb;
          out[OFF_U   + c] = u_in[c];
          out[OFF_BZ  + c] = bz_in[c];
        }
      }
    }
    int g = bid*NTH + tid;
    ((float4*)(out + OFF_CZ))[g] = ((const float4*)Cz_in)[g];
    const float4* Pi = (const float4*)P_in;
    float4* Po = (float4*)(out + OFF_P);
    #pragma unroll 4
    for (int k=0;k<(NLAT*NFEAT/4)/(NB*NTH);k++)
      Po[k*NB*NTH + g] = Pi[k*NB*NTH + g];
    __syncthreads();
    if (tid == 0) stvu(&g_sig[bid], base + 1000u);
    return;
  }

  /* ---- main scan: ONE grid barrier per component ----
     invariants A=xr.Wz, B=|Wz|^2, Q=|xr|^2 give, for any u:
       xr.wz(u)   = A + u*Q
       |wz(u)|^2  = B + 2u*A + u^2*Q
     so both inner power-iteration steps need only one grid reduction. */
  for (int c=0;c<NLAT;c++){
    const size_t frow = (size_t)c*(NFEAT/4) + bid*FB4 + tid;
    float4 w = wnext;

    /* per-thread invariant partials, block-reduce, post to mailbox */
    float4 pr = bred_all(d4(xr,w), d4(w,w), d4(xr,xr), s_w);
    if (tid == 0){
      stv4(&g_part[c*NB + bid], pr);
      __threadfence();
      stvu(&g_sig[bid], base + (unsigned)c + 1u);
    }

    /* prefetch while others arrive: Cz row, P slice, next Wz, scalars */
    float4 c0[YIT];
    #pragma unroll
    for (int k=0;k<YIT;k++)
      c0[k] = ((const float4*)Cz_in)[(size_t)c*YF4 + k*NTH + tid];
    float4 pcur = ((const float4*)P_in)[frow];
    if (c+1 < NLAT)
      wnext = ((const float4*)Wz_in)[frow + (NFEAT/4)];
    const float u0   = u_in[c];
    const float tss0 = tss_in[c];
    const float bz0  = bz_in[c];

    /* wait + grid sum of (A,B,Q) */
    float4 g = grid_gather(c, base + (unsigned)c + 1u, s_w);
    const float A = g.x, B = g.y, Q = g.z;

    /* inner iteration 1 scalars */
    float tz1  = (A + u0*Q) / (sqrtf(fmaxf(B + 2.f*u0*A + u0*u0*Q, 0.f)) + EPSV);
    float tss1 = tss0 + tz1*tz1;
    float t1   = tz1 / sqrtf(tss1);

    /* target pass 1 (local, block-redundant) */
    float c2=0.f, cy=0.f;
    #pragma unroll
    for (int k=0;k<YIT;k++){
      float4 cz = f4fma(yr[k], t1, c0[k]);
      c2 += d4(cz,cz); cy += d4(yr[k],cz);
    }
    {
      float4 r = bred_all(c2, cy, 0.f, s_w);
      c2 = r.x; cy = r.y;
    }
    const float u1 = cy / sqrtf(c2);

    /* inner iteration 2 scalars (no second grid reduction) */
    float tz   = (A + u1*Q) / (sqrtf(fmaxf(B + 2.f*u1*A + u1*u1*Q, 0.f)) + EPSV);
    float tss_ = tss0 + tz*tz;
    float t    = tz / sqrtf(tss_);

    /* write Wz row: wz2 = Wz + u1*xr */
    ((float4*)(out + OFF_WZ))[frow] = f4fma(xr, u1, w);

    /* target pass 2 (local) */
    float4 czk[YIT];
    c2 = 0.f; cy = 0.f;
    #pragma unroll
    for (int k=0;k<YIT;k++){
      czk[k] = f4fma(yr[k], t, c0[k]);
      c2 += d4(czk[k],czk[k]); cy += d4(yr[k],czk[k]);
    }
    {
      float4 r = bred_all(c2, cy, 0.f, s_w);
      c2 = r.x; cy = r.y;
    }
    const float u_f    = cy / sqrtf(c2);
    const float bz_new = bz0 + u_f*tz;
    const float b      = bz_new / sqrtf(tss_);
    const float kk     = b * t / sqrtf(c2);   /* b*t/||cz|| */

    if (bid == c){                             /* one writer block per comp */
      #pragma unroll
      for (int k=0;k<YIT;k++)
        ((float4*)(out + OFF_CZ))[(size_t)c*YF4 + k*NTH + tid] = czk[k];
      if (tid == 0){
        out[OFF_U   + c] = u_f;
        out[OFF_TSS + c] = tss_;
        out[OFF_BZ  + c] = bz_new;
      }
    }

    /* deflations + P update */
    #pragma unroll
    for (int k=0;k<YIT;k++)
      yr[k] = f4fma(czk[k], -kk, yr[k]);       /* yr -= b*t*C_i */

    float4 pn = f4fma(xr, t, pcur);            /* P_new = P + t*xr */
    ((float4*)(out + OFF_P))[frow] = pn;
    xr = f4fma(pn, -t, xr);                    /* xr -= t*P_new */
  }

  /* leave uniform sentinel so next launch reads a uniform epoch base */
  __syncthreads();
  if (tid == 0) stvu(&g_sig[bid], base + 1000u);
}

extern "C" void kernel_launch(void* const* d_in, const int* in_sizes, int n_in,
                              void* d_out, int out_size)
{
  (void)in_sizes; (void)n_in; (void)out_size;
  ipls_kernel<<<NB, NTH>>>(
      (const float*)d_in[0],  (const float*)d_in[1],
      (const float*)d_in[2],  (const float*)d_in[3],
      (const float*)d_in[4],  (const float*)d_in[5],
      (const float*)d_in[6],  (const float*)d_in[7],
      (const float*)d_in[8],  (const float*)d_in[9],
      (const int*)  d_in[10], (float*)d_out);
}

// round 4
// speedup vs baseline: 2.5319x; 1.1276x over previous
#include <cuda_runtime.h>

#define NFEAT 262144
#define NTGT  8192
#define NLAT  32
#define NB    128
#define NTH   512
#define FB4   (NFEAT/NB/4)   /* 512 float4 per block = 1 per thread */
#define YF4   (NTGT/4)       /* 2048 float4 = full target vector    */
#define YIT   (YF4/NTH)      /* 4 float4 per thread                 */
#define YSL   (YF4/NB)       /* 16 float4 block slice of muy        */
#define EPSV  1e-7f

/* output offsets (floats) */
#define OFF_MUY  (NFEAT)
#define OFF_U    (NFEAT + NTGT)
#define OFF_WZ   (OFF_U + NLAT)
#define OFF_CZ   (OFF_WZ + NLAT*NFEAT)
#define OFF_TSS  (OFF_CZ + NLAT*NTGT)
#define OFF_BZ   (OFF_TSS + NLAT)
#define OFF_P    (OFF_BZ + NLAT)

/* mailbox: (NLAT+1) phases x NB blocks x 2 float4 */
__device__ float4   g_part[(NLAT+1)*NB*2];
__device__ unsigned g_sig[NB];   /* monotone per-block signal */

static __device__ __forceinline__ unsigned ld_acq(const unsigned* p){
  unsigned v;
  asm volatile("ld.acquire.gpu.global.u32 %0, [%1];" : "=r"(v) : "l"(p) : "memory");
  return v;
}
static __device__ __forceinline__ void st_rel(unsigned* p, unsigned v){
  asm volatile("st.release.gpu.global.u32 [%0], %1;" :: "l"(p), "r"(v) : "memory");
}
static __device__ __forceinline__ float4 ldcg4(const float4* p){
  float4 v;
  asm volatile("ld.global.cg.v4.f32 {%0,%1,%2,%3}, [%4];"
               : "=f"(v.x),"=f"(v.y),"=f"(v.z),"=f"(v.w) : "l"(p) : "memory");
  return v;
}
static __device__ __forceinline__ void stcg4(float4* p, float4 v){
  asm volatile("st.global.cg.v4.f32 [%0], {%1,%2,%3,%4};"
               :: "l"(p),"f"(v.x),"f"(v.y),"f"(v.z),"f"(v.w) : "memory");
}

static __device__ __forceinline__ float d4(float4 a, float4 b){
  return fmaf(a.x,b.x, fmaf(a.y,b.y, fmaf(a.z,b.z, a.w*b.w)));
}
static __device__ __forceinline__ float4 f4fma(float4 a, float s, float4 b){
  float4 r; r.x=fmaf(a.x,s,b.x); r.y=fmaf(a.y,s,b.y);
  r.z=fmaf(a.z,s,b.z); r.w=fmaf(a.w,s,b.w); return r;
}
/* r = s*a + m*b */
static __device__ __forceinline__ float4 f4axpby(float s, float4 a, float m, float4 b){
  float4 r;
  r.x = fmaf(a.x,s, m*b.x); r.y = fmaf(a.y,s, m*b.y);
  r.z = fmaf(a.z,s, m*b.z); r.w = fmaf(a.w,s, m*b.w);
  return r;
}

/* block-wide reduce of 8 floats; result broadcast to ALL threads */
static __device__ __forceinline__ void bred_all8(float4& a, float4& b, float4* s_w){
  __syncthreads();
  #pragma unroll
  for (int o=16;o>0;o>>=1){
    a.x += __shfl_xor_sync(0xffffffffu,a.x,o);
    a.y += __shfl_xor_sync(0xffffffffu,a.y,o);
    a.z += __shfl_xor_sync(0xffffffffu,a.z,o);
    a.w += __shfl_xor_sync(0xffffffffu,a.w,o);
    b.x += __shfl_xor_sync(0xffffffffu,b.x,o);
    b.y += __shfl_xor_sync(0xffffffffu,b.y,o);
    b.z += __shfl_xor_sync(0xffffffffu,b.z,o);
    b.w += __shfl_xor_sync(0xffffffffu,b.w,o);
  }
  int w = threadIdx.x >> 5;
  if ((threadIdx.x & 31) == 0){ s_w[w] = a; s_w[16+w] = b; }
  __syncthreads();
  a = s_w[0]; b = s_w[16];
  #pragma unroll
  for (int i=1;i<16;i++){
    float4 ta = s_w[i], tb = s_w[16+i];
    a.x+=ta.x; a.y+=ta.y; a.z+=ta.z; a.w+=ta.w;
    b.x+=tb.x; b.y+=tb.y; b.z+=tb.z; b.w+=tb.w;
  }
  __syncthreads();
}

/* wait for all NB blocks at phase sigval, sum their 5-float partials */
static __device__ __forceinline__ void gather5(int ph, unsigned sigval,
                                               float4& A4, float& r5, float4* s_w){
  __syncthreads();
  if (threadIdx.x < NB){
    while (ld_acq(&g_sig[threadIdx.x]) < sigval) { }
    const float4* mp = &g_part[(ph*NB + threadIdx.x)*2];
    float4 a = ldcg4(mp);
    float  b = ldcg4(mp+1).x;
    #pragma unroll
    for (int o=16;o>0;o>>=1){
      a.x += __shfl_xor_sync(0xffffffffu,a.x,o);
      a.y += __shfl_xor_sync(0xffffffffu,a.y,o);
      a.z += __shfl_xor_sync(0xffffffffu,a.z,o);
      a.w += __shfl_xor_sync(0xffffffffu,a.w,o);
      b   += __shfl_xor_sync(0xffffffffu,b,o);
    }
    if ((threadIdx.x & 31) == 0){
      s_w[threadIdx.x>>5] = a;
      s_w[8 + (threadIdx.x>>5)] = make_float4(b,0.f,0.f,0.f);
    }
  }
  __syncthreads();
  float4 a = s_w[0]; float b = s_w[8].x;
  #pragma unroll
  for (int i=1;i<4;i++){
    float4 t = s_w[i];
    a.x+=t.x; a.y+=t.y; a.z+=t.z; a.w+=t.w;
    b += s_w[8+i].x;
  }
  __syncthreads();
  A4 = a; r5 = b;
}

__global__ void __launch_bounds__(NTH, 1)
ipls_kernel(const float* __restrict__ x,      const float* __restrict__ y,
            const float* __restrict__ mux,    const float* __restrict__ muy,
            const float* __restrict__ u_in,   const float* __restrict__ Wz_in,
            const float* __restrict__ Cz_in,  const float* __restrict__ tss_in,
            const float* __restrict__ bz_in,  const float* __restrict__ P_in,
            const int* __restrict__ n_in,     float* __restrict__ out)
{
  __shared__ float4 s_w[32];

  const int tid = threadIdx.x, bid = blockIdx.x;
  const unsigned base = ld_acq(&g_sig[bid]);   /* uniform epoch base */

  const int n   = n_in[0];
  const float fn1  = (float)(n + 1);
  const float fden = (float)(n + 2);

  /* ---- init: feature slice in registers ---- */
  float4 xr;
  {
    int gi = bid*FB4 + tid;
    float4 xv = ((const float4*)x)[gi];
    float4 mv = ((const float4*)mux)[gi];
    float4 mu;
    mu.x = (mv.x*fn1 + xv.x)/fden; mu.y = (mv.y*fn1 + xv.y)/fden;
    mu.z = (mv.z*fn1 + xv.z)/fden; mu.w = (mv.w*fn1 + xv.w)/fden;
    ((float4*)out)[gi] = mu;
    xr.x = xv.x-mu.x; xr.y = xv.y-mu.y; xr.z = xv.z-mu.z; xr.w = xv.w-mu.w;
  }

  /* ---- init: FULL yr in registers (block-redundant) ---- */
  float4 yr[YIT];
  #pragma unroll
  for (int k=0;k<YIT;k++){
    int gi = k*NTH + tid;
    float4 yv = ((const float4*)y)[gi];
    float4 mv = ((const float4*)muy)[gi];
    float4 mu;
    mu.x = (mv.x*fn1 + yv.x)/fden; mu.y = (mv.y*fn1 + yv.y)/fden;
    mu.z = (mv.z*fn1 + yv.z)/fden; mu.w = (mv.w*fn1 + yv.w)/fden;
    yr[k].x = yv.x-mu.x; yr[k].y = yv.y-mu.y;
    yr[k].z = yv.z-mu.z; yr[k].w = yv.w-mu.w;
  }
  if (tid < YSL){
    int gi = bid*YSL + tid;
    float4 yv = ((const float4*)y)[gi];
    float4 mv = ((const float4*)muy)[gi];
    float4 mu;
    mu.x = (mv.x*fn1 + yv.x)/fden; mu.y = (mv.y*fn1 + yv.y)/fden;
    mu.z = (mv.z*fn1 + yv.z)/fden; mu.w = (mv.w*fn1 + yv.w)/fden;
    ((float4*)(out + OFF_MUY))[gi] = mu;
  }

  /* prologue prefetch */
  float4 wcur = ((const float4*)Wz_in)[bid*FB4 + tid];
  float4 wnext= ((const float4*)Wz_in)[(size_t)(NFEAT/4) + bid*FB4 + tid];
  float4 pc   = ((const float4*)P_in)[bid*FB4 + tid];
  float4 c0[YIT];
  #pragma unroll
  for (int k=0;k<YIT;k++)
    c0[k] = ((const float4*)Cz_in)[k*NTH + tid];

  /* prologue reduce: (A0, B0, Q0 | G) */
  float G;
  {
    float gg = 0.f;
    #pragma unroll
    for (int k=0;k<YIT;k++) gg += d4(yr[k], yr[k]);
    float4 a = make_float4(d4(xr,wcur), d4(wcur,wcur), d4(xr,xr), gg);
    float4 b = make_float4(0.f,0.f,0.f,0.f);
    bred_all8(a, b, s_w);
    G = a.w;   /* full-vector norm: block-complete */
    if (tid == 0){
      stcg4(&g_part[(0*NB + bid)*2],   a);
      stcg4(&g_part[(0*NB + bid)*2+1], b);
      st_rel(&g_sig[bid], base + 1u);
    }
  }

  /* ---- burn-in path (n_new <= 3): only Wz and t_sq_sum change ---- */
  if (n + 1 <= 3){
    for (int c=0;c<NLAT;c++){
      float u_c = u_in[c];
      float4 w = (c==0) ? wcur : ((c==1) ? wnext
               : ((const float4*)Wz_in)[(size_t)c*(NFEAT/4) + bid*FB4 + tid]);
      float4 wz = f4fma(xr, u_c, w);
      ((float4*)(out + OFF_WZ))[(size_t)c*(NFEAT/4) + bid*FB4 + tid] = wz;
      float4 a = make_float4(d4(xr,wz), d4(wz,wz), 0.f, 0.f);
      float4 b = make_float4(0.f,0.f,0.f,0.f);
      bred_all8(a, b, s_w);
      if (tid == 0) stcg4(&g_part[((c+1)*NB + bid)*2], a);
    }
    if (tid == 0) st_rel(&g_sig[bid], base + NLAT + 1u);

    if (bid == 0){
      for (int c=0;c<NLAT;c++){
        float4 ga; float g5;
        gather5(c+1, base + NLAT + 1u, ga, g5, s_w);
        if (tid == 0){
          float tzb = ga.x / (sqrtf(ga.y) + EPSV);
          out[OFF_TSS + c] = tss_in[c] + tzb*tzb;
          out[OFF_U   + c] = u_in[c];
          out[OFF_BZ  + c] = bz_in[c];
        }
      }
    }
    int g = bid*NTH + tid;
    ((float4*)(out + OFF_CZ))[g] = ((const float4*)Cz_in)[g];
    const float4* Pi = (const float4*)P_in;
    float4* Po = (float4*)(out + OFF_P);
    #pragma unroll 4
    for (int k=0;k<(NLAT*NFEAT/4)/(NB*NTH);k++)
      Po[k*NB*NTH + g] = Pi[k*NB*NTH + g];
    __syncthreads();
    if (tid == 0) st_rel(&g_sig[bid], base + 1000u);
    return;
  }

  /* gather prologue invariants */
  float A, B, Q;
  {
    float4 ga; float g5;
    gather5(0, base + 1u, ga, g5, s_w);
    A = ga.x; B = ga.y; Q = ga.z;
  }

  /* ---- main scan: 1 block reduce + 1 overlapped grid gather per comp ---- */
  for (int c=0;c<NLAT;c++){
    const size_t frow = (size_t)c*(NFEAT/4) + bid*FB4 + tid;
    const float u0   = u_in[c];
    const float tss0 = tss_in[c];
    const float bz0  = bz_in[c];

    /* top: raw dots for NEXT comp (t-independent) + E,F for this comp */
    float E = 0.f, F = 0.f;
    #pragma unroll
    for (int k=0;k<YIT;k++){
      E += d4(c0[k], c0[k]);
      F += d4(c0[k], yr[k]);
    }
    {
      float4 a = make_float4(d4(xr,wnext), d4(pc,wnext), d4(xr,pc), d4(pc,pc));
      float4 b = make_float4(d4(wnext,wnext), E, F, 0.f);
      bred_all8(a, b, s_w);
      if (c+1 < NLAT && tid == 0){
        stcg4(&g_part[((c+1)*NB + bid)*2],   a);
        stcg4(&g_part[((c+1)*NB + bid)*2+1], b);
        st_rel(&g_sig[bid], base + 2u + (unsigned)c);
      }
      E = b.y; F = b.z;
    }

    /* scalar chain (all grid-complete invariants) */
    float tz1  = (A + u0*Q) / (sqrtf(fmaxf(B + 2.f*u0*A + u0*u0*Q, 0.f)) + EPSV);
    float tss1 = tss0 + tz1*tz1;
    float t1   = tz1 / sqrtf(tss1);
    float c21  = fmaxf(E + 2.f*t1*F + t1*t1*G, 0.f);
    float u1   = (F + t1*G) / sqrtf(c21);

    float tz   = (A + u1*Q) / (sqrtf(fmaxf(B + 2.f*u1*A + u1*u1*Q, 0.f)) + EPSV);
    float tss_ = tss0 + tz*tz;
    float t    = tz / sqrtf(tss_);
    float c2   = fmaxf(E + 2.f*t*F + t*t*G, 0.f);
    float rc2  = rsqrtf(c2);
    float u_f  = (F + t*G) * rc2;
    float bz_new = bz0 + u_f*tz;
    float bb   = bz_new / sqrtf(tss_);
    float kk   = bb * t * rc2;          /* b*t/||cz|| */
    float ss   = 1.f - kk*t;            /* yr' = ss*yr - kk*Cz */

    /* vector work */
    ((float4*)(out + OFF_WZ))[frow] = f4fma(xr, u1, wcur);

    if (bid == c){                       /* single writer for Cz row + scalars */
      #pragma unroll
      for (int k=0;k<YIT;k++)
        ((float4*)(out + OFF_CZ))[(size_t)c*YF4 + k*NTH + tid] =
            f4fma(yr[k], t, c0[k]);
      if (tid == 0){
        out[OFF_U   + c] = u_f;
        out[OFF_TSS + c] = tss_;
        out[OFF_BZ  + c] = bz_new;
      }
    }

    #pragma unroll
    for (int k=0;k<YIT;k++)
      yr[k] = f4axpby(ss, yr[k], -kk, c0[k]);

    float4 pn = f4fma(xr, t, pc);
    ((float4*)(out + OFF_P))[frow] = pn;
    xr = f4fma(pn, -t, xr);

    G = ss*ss*G - 2.f*ss*kk*F + kk*kk*E;

    /* prefetch next component's operands (issued before the gather wait) */
    wcur = wnext;
    if (c+2 < NLAT)
      wnext = ((const float4*)Wz_in)[(size_t)(c+2)*(NFEAT/4) + bid*FB4 + tid];
    if (c+1 < NLAT){
      pc = ((const float4*)P_in)[(size_t)(c+1)*(NFEAT/4) + bid*FB4 + tid];
      #pragma unroll
      for (int k=0;k<YIT;k++)
        c0[k] = ((const float4*)Cz_in)[(size_t)(c+1)*YF4 + k*NTH + tid];

      /* gather next comp's raw dots and apply t-algebra */
      float4 ga; float r5;
      gather5(c+1, base + 2u + (unsigned)c, ga, r5, s_w);
      float dd = 1.f - t*t;
      A = dd*ga.x - t*ga.y;
      Q = dd*dd*Q - 2.f*t*dd*ga.z + t*t*ga.w;
      B = r5;
    }
  }

  __syncthreads();
  if (tid == 0) st_rel(&g_sig[bid], base + 1000u);
}

extern "C" void kernel_launch(void* const* d_in, const int* in_sizes, int n_in,
                              void* d_out, int out_size)
{
  (void)in_sizes; (void)n_in; (void)out_size;
  ipls_kernel<<<NB, NTH>>>(
      (const float*)d_in[0],  (const float*)d_in[1],
      (const float*)d_in[2],  (const float*)d_in[3],
      (const float*)d_in[4],  (const float*)d_in[5],
      (const float*)d_in[6],  (const float*)d_in[7],
      (const float*)d_in[8],  (const float*)d_in[9],
      (const int*)  d_in[10], (float*)d_out);
}